// round 12
// baseline (speedup 1.0000x reference)
#include <cuda_runtime.h>
#include <cuda_bf16.h>
#include <cuda_fp16.h>
#include <cstdint>

// Problem constants
#define Bz 8
#define Tz 1024
#define Cz 768
#define NHz 12
#define HDz 64
#define Mz (Bz * Tz)          // 8192
#define N_QKV (3 * Cz)        // 2304

// Scratch in device globals (no allocations allowed)
__device__ __half g_xh[(size_t)Mz * Cz], g_xl[(size_t)Mz * Cz];
__device__ __half g_wah[(size_t)N_QKV * Cz];
__device__ __nv_bfloat16 g_qkvh[(size_t)Mz * N_QKV], g_qkvl[(size_t)Mz * N_QKV];
__device__ __nv_bfloat16 g_ath[(size_t)Mz * Cz], g_atl[(size_t)Mz * Cz];
__device__ __nv_bfloat16 g_wph[(size_t)Cz * Cz], g_wpl[(size_t)Cz * Cz];

// ---------------------------------------------------------------------------
// Base-ISA helpers
// ---------------------------------------------------------------------------
__device__ __forceinline__ uint32_t smem_u32(const void* p) {
    uint32_t a;
    asm("{ .reg .u64 t; cvta.to.shared.u64 t, %1; cvt.u32.u64 %0, t; }"
        : "=r"(a) : "l"(p));
    return a;
}
__device__ __forceinline__ void cpa16(uint32_t s, const void* g) {
    asm volatile("cp.async.cg.shared.global [%0], [%1], 16;" :: "r"(s), "l"(g));
}
#define CPCOMMIT() asm volatile("cp.async.commit_group;" ::: "memory")
template <int N> __device__ __forceinline__ void cpwait() {
    asm volatile("cp.async.wait_group %0;" :: "n"(N) : "memory");
}
__device__ __forceinline__ void ldsm4(uint32_t* r, uint32_t addr) {
    asm volatile("ldmatrix.sync.aligned.m8n8.x4.shared.b16 {%0,%1,%2,%3}, [%4];"
                 : "=r"(r[0]), "=r"(r[1]), "=r"(r[2]), "=r"(r[3]) : "r"(addr));
}
__device__ __forceinline__ void ldsm4t(uint32_t* r, uint32_t addr) {
    asm volatile("ldmatrix.sync.aligned.m8n8.x4.trans.shared.b16 {%0,%1,%2,%3}, [%4];"
                 : "=r"(r[0]), "=r"(r[1]), "=r"(r[2]), "=r"(r[3]) : "r"(addr));
}
__device__ __forceinline__ void mma_bf16(float* d, const uint32_t* a,
                                         uint32_t b0, uint32_t b1) {
    asm("mma.sync.aligned.m16n8k16.row.col.f32.bf16.bf16.f32 "
        "{%0,%1,%2,%3}, {%4,%5,%6,%7}, {%8,%9}, {%0,%1,%2,%3};"
        : "+f"(d[0]), "+f"(d[1]), "+f"(d[2]), "+f"(d[3])
        : "r"(a[0]), "r"(a[1]), "r"(a[2]), "r"(a[3]), "r"(b0), "r"(b1));
}
__device__ __forceinline__ void mma_f16(float* d, const uint32_t* a,
                                        uint32_t b0, uint32_t b1) {
    asm("mma.sync.aligned.m16n8k16.row.col.f32.f16.f16.f32 "
        "{%0,%1,%2,%3}, {%4,%5,%6,%7}, {%8,%9}, {%0,%1,%2,%3};"
        : "+f"(d[0]), "+f"(d[1]), "+f"(d[2]), "+f"(d[3])
        : "r"(a[0]), "r"(a[1]), "r"(a[2]), "r"(a[3]), "r"(b0), "r"(b1));
}
__device__ __forceinline__ void split_bf16(float v, __nv_bfloat16& h, __nv_bfloat16& l) {
    h = __float2bfloat16(v);
    l = __float2bfloat16(v - __bfloat162float(h));
}
__device__ __forceinline__ void split_f16(float v, __half& h, __half& l) {
    h = __float2half(v);
    l = __float2half(v - __half2float(h));
}

// ---------------------------------------------------------------------------
// Prep kernels
// ---------------------------------------------------------------------------
__global__ __launch_bounds__(256)
void split_f16_kernel(const float* __restrict__ in, __half* __restrict__ oh,
                      __half* __restrict__ ol, int n4) {
    int i = blockIdx.x * 256 + threadIdx.x;
    if (i >= n4) return;
    float4 v = *(const float4*)(in + (size_t)i * 4);
    __half h[4], l[4];
    split_f16(v.x, h[0], l[0]);
    split_f16(v.y, h[1], l[1]);
    split_f16(v.z, h[2], l[2]);
    split_f16(v.w, h[3], l[3]);
    *(uint2*)(oh + (size_t)i * 4) = *(uint2*)h;
    *(uint2*)(ol + (size_t)i * 4) = *(uint2*)l;
}

// W [K,N] fp32 -> transposed fp16 [N,K] (hi only)
__global__ void tsplit_f16_kernel(const float* __restrict__ W,
                                  __half* __restrict__ oh, int K, int N) {
    __shared__ float t[32][33];
    int n0 = blockIdx.x * 32, k0 = blockIdx.y * 32;
    int tx = threadIdx.x, ty = threadIdx.y;
#pragma unroll
    for (int r = 0; r < 32; r += 8)
        t[ty + r][tx] = W[(size_t)(k0 + ty + r) * N + n0 + tx];
    __syncthreads();
#pragma unroll
    for (int r = 0; r < 32; r += 8) {
        oh[(size_t)(n0 + ty + r) * K + k0 + tx] = __float2half(t[tx][ty + r]);
    }
}

// W [K,N] fp32 -> transposed split bf16 [N,K]
__global__ void tsplit_kernel(const float* __restrict__ W,
                              __nv_bfloat16* __restrict__ oh,
                              __nv_bfloat16* __restrict__ ol, int K, int N) {
    __shared__ float t[32][33];
    int n0 = blockIdx.x * 32, k0 = blockIdx.y * 32;
    int tx = threadIdx.x, ty = threadIdx.y;
#pragma unroll
    for (int r = 0; r < 32; r += 8)
        t[ty + r][tx] = W[(size_t)(k0 + ty + r) * N + n0 + tx];
    __syncthreads();
#pragma unroll
    for (int r = 0; r < 32; r += 8) {
        float v = t[tx][ty + r];
        __nv_bfloat16 h, l;
        split_bf16(v, h, l);
        size_t o = (size_t)(n0 + ty + r) * K + k0 + tx;
        oh[o] = h;
        ol[o] = l;
    }
}

__device__ __forceinline__ uint32_t sw64(int row, int c16) {
    return (uint32_t)(row * 64 + ((c16 ^ ((row >> 1) & 3)) * 16));
}

// ---------------------------------------------------------------------------
// fp16 2-term GEMM (QKV): C = (Ah+Al) @ Bh^T + bias -> split bf16 out.
// 128x128 CTA tile, 8 warps (64x32 each), BK=32, 3-stage cp.async ring.
// Stage = Ah(8K) + Al(8K) + Bh(8K) = 24KB.
// ---------------------------------------------------------------------------
#define STAGE2_B 24576
#define NSTAGE 3
#define OFF2_AH 0
#define OFF2_AL 8192
#define OFF2_BH 16384
#define GEMM2_SMEM (NSTAGE * STAGE2_B)   // 73728

__global__ __launch_bounds__(256)
void tc_gemm_f16(const __half* __restrict__ Ah, const __half* __restrict__ Al,
                 const __half* __restrict__ Bh, const float* __restrict__ bias,
                 __nv_bfloat16* __restrict__ Ch, __nv_bfloat16* __restrict__ Cl,
                 int N, int K) {
    extern __shared__ char smp[];
    const uint32_t sb = smem_u32(smp);

    const int tid = threadIdx.x;
    const int wid = tid >> 5;
    const int lane = tid & 31;
    const int wm = wid & 1;
    const int wn = wid >> 1;
    const int bm = blockIdx.y * 128;
    const int bn = blockIdx.x * 128;
    const int NKC = K >> 5;

    const int lrow0 = tid >> 2;    // 0..63
    const int lc16 = tid & 3;      // 0..3

    const int rowA = wm * 64 + (lane & 15);
    const int rowB = wn * 32 + (lane & 15);
    const int rswA = (rowA >> 1) & 3;
    const int rswB = (rowB >> 1) & 3;
    const int chalf = lane >> 4;

    float acc[4][4][4];
#pragma unroll
    for (int i = 0; i < 4; i++)
#pragma unroll
        for (int j = 0; j < 4; j++)
#pragma unroll
            for (int e = 0; e < 4; e++) acc[i][j][e] = 0.0f;

    auto load_stage = [&](int kc) {
        const uint32_t stg = sb + (uint32_t)(kc % NSTAGE) * STAGE2_B;
        const int ke = kc * 32;
#pragma unroll
        for (int v = 0; v < 2; v++) {
            int row = lrow0 + v * 64;
            uint32_t swo = sw64(row, lc16);
            size_t ga = (size_t)(bm + row) * K + ke + lc16 * 8;
            size_t gb = (size_t)(bn + row) * K + ke + lc16 * 8;
            cpa16(stg + OFF2_AH + swo, Ah + ga);
            cpa16(stg + OFF2_AL + swo, Al + ga);
            cpa16(stg + OFF2_BH + swo, Bh + gb);
        }
    };

    load_stage(0);
    CPCOMMIT();
    load_stage(1);
    CPCOMMIT();

    for (int kc = 0; kc < NKC; kc++) {
        if (kc + 1 < NKC) cpwait<1>();
        else              cpwait<0>();
        __syncthreads();              // publish stage kc; readers of kc-1 done
        if (kc + 2 < NKC) {
            load_stage(kc + 2);
            CPCOMMIT();
        }

        const uint32_t stg = sb + (uint32_t)(kc % NSTAGE) * STAGE2_B;
#pragma unroll
        for (int s16 = 0; s16 < 2; s16++) {
            const int c16 = s16 * 2 + chalf;
            const uint32_t aswc = (uint32_t)((c16 ^ rswA) * 16);
            const uint32_t bswc = (uint32_t)((c16 ^ rswB) * 16);

            uint32_t ah[4][4], al[4][4], bh[2][4];
#pragma unroll
            for (int i = 0; i < 4; i++) {
                uint32_t ro = (uint32_t)((rowA + 16 * i) * 64);
                ldsm4(ah[i], stg + OFF2_AH + ro + aswc);
                ldsm4(al[i], stg + OFF2_AL + ro + aswc);
            }
#pragma unroll
            for (int g = 0; g < 2; g++) {
                uint32_t ro = (uint32_t)((rowB + 16 * g) * 64);
                ldsm4(bh[g], stg + OFF2_BH + ro + bswc);
            }

#pragma unroll
            for (int i = 0; i < 4; i++)
#pragma unroll
                for (int g = 0; g < 2; g++)
#pragma unroll
                    for (int h = 0; h < 2; h++)
                        mma_f16(acc[i][g * 2 + h], ah[i], bh[g][h], bh[g][h + 2]);
#pragma unroll
            for (int i = 0; i < 4; i++)
#pragma unroll
                for (int g = 0; g < 2; g++)
#pragma unroll
                    for (int h = 0; h < 2; h++)
                        mma_f16(acc[i][g * 2 + h], al[i], bh[g][h], bh[g][h + 2]);
        }
    }

    const int lane4 = lane >> 2;
    const int lm2 = (lane & 3) * 2;
#pragma unroll
    for (int i = 0; i < 4; i++) {
        int r0 = bm + wm * 64 + i * 16 + lane4;
#pragma unroll
        for (int j = 0; j < 4; j++) {
            int cc = bn + wn * 32 + j * 8 + lm2;
            float b0 = bias[cc], b1 = bias[cc + 1];
            float v00 = acc[i][j][0] + b0, v01 = acc[i][j][1] + b1;
            float v10 = acc[i][j][2] + b0, v11 = acc[i][j][3] + b1;
            __nv_bfloat16 h0, l0, h1, l1;
            split_bf16(v00, h0, l0);
            split_bf16(v01, h1, l1);
            __nv_bfloat162 ph = {h0, h1}, pl = {l0, l1};
            *(uint32_t*)&Ch[(size_t)r0 * N + cc] = *(uint32_t*)&ph;
            *(uint32_t*)&Cl[(size_t)r0 * N + cc] = *(uint32_t*)&pl;
            split_bf16(v10, h0, l0);
            split_bf16(v11, h1, l1);
            __nv_bfloat162 qh = {h0, h1}, ql = {l0, l1};
            *(uint32_t*)&Ch[(size_t)(r0 + 8) * N + cc] = *(uint32_t*)&qh;
            *(uint32_t*)&Cl[(size_t)(r0 + 8) * N + cc] = *(uint32_t*)&ql;
        }
    }
}

// ---------------------------------------------------------------------------
// bf16 3-term GEMM (proj): R9-verified, fp32 out.
// ---------------------------------------------------------------------------
#define STAGE_B 32768
#define OFF_AH 0
#define OFF_AL 8192
#define OFF_BH 16384
#define OFF_BL 24576
#define GEMM_SMEM (NSTAGE * STAGE_B)     // 98304

__global__ __launch_bounds__(256)
void tc_gemm(const __nv_bfloat16* __restrict__ Ah, const __nv_bfloat16* __restrict__ Al,
             const __nv_bfloat16* __restrict__ Bh, const __nv_bfloat16* __restrict__ Bl,
             const float* __restrict__ bias, float* __restrict__ C, int N, int K) {
    extern __shared__ char smp[];
    const uint32_t sb = smem_u32(smp);

    const int tid = threadIdx.x;
    const int wid = tid >> 5;
    const int lane = tid & 31;
    const int wm = wid & 1;
    const int wn = wid >> 1;
    const int bm = blockIdx.y * 128;
    const int bn = blockIdx.x * 128;
    const int NKC = K >> 5;

    const int lrow0 = tid >> 2;
    const int lc16 = tid & 3;

    const int rowA = wm * 64 + (lane & 15);
    const int rowB = wn * 32 + (lane & 15);
    const int rswA = (rowA >> 1) & 3;
    const int rswB = (rowB >> 1) & 3;
    const int chalf = lane >> 4;

    float acc[4][4][4];
#pragma unroll
    for (int i = 0; i < 4; i++)
#pragma unroll
        for (int j = 0; j < 4; j++)
#pragma unroll
            for (int e = 0; e < 4; e++) acc[i][j][e] = 0.0f;

    auto load_stage = [&](int kc) {
        const uint32_t stg = sb + (uint32_t)(kc % NSTAGE) * STAGE_B;
        const int ke = kc * 32;
#pragma unroll
        for (int v = 0; v < 2; v++) {
            int row = lrow0 + v * 64;
            uint32_t swo = sw64(row, lc16);
            size_t ga = (size_t)(bm + row) * K + ke + lc16 * 8;
            size_t gb = (size_t)(bn + row) * K + ke + lc16 * 8;
            cpa16(stg + OFF_AH + swo, Ah + ga);
            cpa16(stg + OFF_AL + swo, Al + ga);
            cpa16(stg + OFF_BH + swo, Bh + gb);
            cpa16(stg + OFF_BL + swo, Bl + gb);
        }
    };

    load_stage(0);
    CPCOMMIT();
    load_stage(1);
    CPCOMMIT();

    for (int kc = 0; kc < NKC; kc++) {
        if (kc + 1 < NKC) cpwait<1>();
        else              cpwait<0>();
        __syncthreads();
        if (kc + 2 < NKC) {
            load_stage(kc + 2);
            CPCOMMIT();
        }

        const uint32_t stg = sb + (uint32_t)(kc % NSTAGE) * STAGE_B;
#pragma unroll
        for (int s16 = 0; s16 < 2; s16++) {
            const int c16 = s16 * 2 + chalf;
            const uint32_t aswc = (uint32_t)((c16 ^ rswA) * 16);
            const uint32_t bswc = (uint32_t)((c16 ^ rswB) * 16);

            uint32_t ah[4][4], al[4][4], bh[2][4], bl[2][4];
#pragma unroll
            for (int i = 0; i < 4; i++) {
                uint32_t ro = (uint32_t)((rowA + 16 * i) * 64);
                ldsm4(ah[i], stg + OFF_AH + ro + aswc);
                ldsm4(al[i], stg + OFF_AL + ro + aswc);
            }
#pragma unroll
            for (int g = 0; g < 2; g++) {
                uint32_t ro = (uint32_t)((rowB + 16 * g) * 64);
                ldsm4(bh[g], stg + OFF_BH + ro + bswc);
                ldsm4(bl[g], stg + OFF_BL + ro + bswc);
            }

#pragma unroll
            for (int i = 0; i < 4; i++)
#pragma unroll
                for (int g = 0; g < 2; g++)
#pragma unroll
                    for (int h = 0; h < 2; h++)
                        mma_bf16(acc[i][g * 2 + h], ah[i], bh[g][h], bh[g][h + 2]);
#pragma unroll
            for (int i = 0; i < 4; i++)
#pragma unroll
                for (int g = 0; g < 2; g++)
#pragma unroll
                    for (int h = 0; h < 2; h++)
                        mma_bf16(acc[i][g * 2 + h], ah[i], bl[g][h], bl[g][h + 2]);
#pragma unroll
            for (int i = 0; i < 4; i++)
#pragma unroll
                for (int g = 0; g < 2; g++)
#pragma unroll
                    for (int h = 0; h < 2; h++)
                        mma_bf16(acc[i][g * 2 + h], al[i], bh[g][h], bh[g][h + 2]);
        }
    }

    const int lane4 = lane >> 2;
    const int lm2 = (lane & 3) * 2;
#pragma unroll
    for (int i = 0; i < 4; i++) {
        int r0 = bm + wm * 64 + i * 16 + lane4;
#pragma unroll
        for (int j = 0; j < 4; j++) {
            int cc = bn + wn * 32 + j * 8 + lm2;
            float b0 = bias[cc], b1 = bias[cc + 1];
            *(float2*)&C[(size_t)r0 * N + cc] = {acc[i][j][0] + b0, acc[i][j][1] + b1};
            *(float2*)&C[(size_t)(r0 + 8) * N + cc] = {acc[i][j][2] + b0, acc[i][j][3] + b1};
        }
    }
}

// ---------------------------------------------------------------------------
// Tensor-core causal flash attention (R7/R9-verified; big q-tiles first)
// ---------------------------------------------------------------------------
#define AOFF_QH 0
#define AOFF_QL 16384
#define AOFF_KV 32768
#define ASTG 32768
#define AOFF_KH 0
#define AOFF_KL 8192
#define AOFF_VH 16384
#define AOFF_VL 24576
#define ATT_SMEM (AOFF_KV + 2 * ASTG)   // 98304

__device__ __forceinline__ uint32_t asw(int row, int c16) {
    return (uint32_t)(row * 128 + ((c16 ^ (row & 7)) * 16));
}

__global__ __launch_bounds__(256)
void attn_tc(const __nv_bfloat16* __restrict__ qh,
             const __nv_bfloat16* __restrict__ ql,
             __nv_bfloat16* __restrict__ oh, __nv_bfloat16* __restrict__ ol) {
    extern __shared__ char smp[];
    const uint32_t sb = smem_u32(smp);

    const int tid = threadIdx.x;
    const int wid = tid >> 5;
    const int lane = tid & 31;
    const int bh = blockIdx.y;
    const int b = bh / NHz;
    const int h = bh % NHz;
    const int q0 = ((int)gridDim.x - 1 - (int)blockIdx.x) * 128;  // big tiles first

    const __nv_bfloat16* qbh = qh + (size_t)b * Tz * N_QKV + h * HDz;
    const __nv_bfloat16* qbl = ql + (size_t)b * Tz * N_QKV + h * HDz;

#pragma unroll
    for (int i = 0; i < 4; i++) {
        int idx = tid + i * 256;
        int row = idx >> 3;
        int c = idx & 7;
        uint32_t swo = asw(row, c);
        size_t g = (size_t)(q0 + row) * N_QKV + c * 8;
        cpa16(sb + AOFF_QH + swo, qbh + g);
        cpa16(sb + AOFF_QL + swo, qbl + g);
    }
    CPCOMMIT();

    auto load_kv = [&](int kt) {
        const uint32_t stg = sb + AOFF_KV + (uint32_t)(kt & 1) * ASTG;
        const int k0 = kt * 64;
#pragma unroll
        for (int v = 0; v < 2; v++) {
            int row = (tid >> 3) + v * 32;
            int c = tid & 7;
            uint32_t swo = asw(row, c);
            size_t g = (size_t)(k0 + row) * N_QKV + c * 8;
            cpa16(stg + AOFF_KH + swo, qbh + g + Cz);
            cpa16(stg + AOFF_KL + swo, qbl + g + Cz);
            cpa16(stg + AOFF_VH + swo, qbh + g + 2 * Cz);
            cpa16(stg + AOFF_VL + swo, qbl + g + 2 * Cz);
        }
    };

    load_kv(0);
    CPCOMMIT();
    cpwait<1>();        // Q arrived
    __syncthreads();

    const int rowQ = wid * 16 + (lane & 15);
    const int chalf = lane >> 4;
    const int grp = lane >> 2;
    const int lm2 = (lane & 3) * 2;

    float oacc[8][4];
#pragma unroll
    for (int nf = 0; nf < 8; nf++)
#pragma unroll
        for (int e = 0; e < 4; e++) oacc[nf][e] = 0.0f;
    float mrow[2] = {-1e30f, -1e30f};
    float lrow[2] = {0.0f, 0.0f};

    const int ntiles = (q0 + 128) / 64;
    for (int kt = 0; kt < ntiles; kt++) {
        if (kt + 1 < ntiles) {
            load_kv(kt + 1);
            CPCOMMIT();
            cpwait<1>();
        } else {
            cpwait<0>();
        }
        __syncthreads();

        const uint32_t stg = sb + AOFF_KV + (uint32_t)(kt & 1) * ASTG;
        const int k0 = kt * 64;

        float sacc[8][4];
#pragma unroll
        for (int nf = 0; nf < 8; nf++)
#pragma unroll
            for (int e = 0; e < 4; e++) sacc[nf][e] = 0.0f;

#pragma unroll
        for (int kc = 0; kc < 4; kc++) {
            int c16 = kc * 2 + chalf;
            uint32_t qad = (uint32_t)(rowQ * 128 + ((c16 ^ (rowQ & 7)) * 16));
            uint32_t qfh[4], qfl[4];
            ldsm4(qfh, sb + AOFF_QH + qad);
            ldsm4(qfl, sb + AOFF_QL + qad);

            uint32_t kh[4][4], kl[4][4];
#pragma unroll
            for (int g = 0; g < 4; g++) {
                int rowK = g * 16 + (lane & 15);
                uint32_t ad = (uint32_t)(rowK * 128 + ((c16 ^ (rowK & 7)) * 16));
                ldsm4(kh[g], stg + AOFF_KH + ad);
                ldsm4(kl[g], stg + AOFF_KL + ad);
            }
#pragma unroll
            for (int g = 0; g < 4; g++)
#pragma unroll
                for (int hh = 0; hh < 2; hh++)
                    mma_bf16(sacc[g * 2 + hh], qfh, kh[g][hh], kh[g][hh + 2]);
#pragma unroll
            for (int g = 0; g < 4; g++)
#pragma unroll
                for (int hh = 0; hh < 2; hh++)
                    mma_bf16(sacc[g * 2 + hh], qfh, kl[g][hh], kl[g][hh + 2]);
#pragma unroll
            for (int g = 0; g < 4; g++)
#pragma unroll
                for (int hh = 0; hh < 2; hh++)
                    mma_bf16(sacc[g * 2 + hh], qfl, kh[g][hh], kh[g][hh + 2]);
        }

        const bool domask = (k0 + 63 > q0);
#pragma unroll
        for (int nf = 0; nf < 8; nf++)
#pragma unroll
            for (int e = 0; e < 4; e++) {
                float s = sacc[nf][e] * 0.125f;
                if (domask) {
                    int kcol = k0 + nf * 8 + lm2 + (e & 1);
                    int qrow = q0 + wid * 16 + grp + ((e >> 1) << 3);
                    if (kcol > qrow) s = -1e30f;
                }
                sacc[nf][e] = s;
            }

#pragma unroll
        for (int r = 0; r < 2; r++) {
            float mt = -1e30f;
#pragma unroll
            for (int nf = 0; nf < 8; nf++)
                mt = fmaxf(mt, fmaxf(sacc[nf][2 * r], sacc[nf][2 * r + 1]));
            mt = fmaxf(mt, __shfl_xor_sync(0xffffffffu, mt, 1));
            mt = fmaxf(mt, __shfl_xor_sync(0xffffffffu, mt, 2));
            float mnew = fmaxf(mrow[r], mt);
            float alpha = __expf(mrow[r] - mnew);
            float ls = 0.0f;
#pragma unroll
            for (int nf = 0; nf < 8; nf++) {
                float p0 = __expf(sacc[nf][2 * r] - mnew);
                float p1 = __expf(sacc[nf][2 * r + 1] - mnew);
                sacc[nf][2 * r] = p0;
                sacc[nf][2 * r + 1] = p1;
                ls += p0 + p1;
            }
            ls += __shfl_xor_sync(0xffffffffu, ls, 1);
            ls += __shfl_xor_sync(0xffffffffu, ls, 2);
            lrow[r] = lrow[r] * alpha + ls;
            mrow[r] = mnew;
#pragma unroll
            for (int nf = 0; nf < 8; nf++) {
                oacc[nf][2 * r] *= alpha;
                oacc[nf][2 * r + 1] *= alpha;
            }
        }

        uint32_t pfh[4][4], pfl[4][4];
#pragma unroll
        for (int kc = 0; kc < 4; kc++) {
#pragma unroll
            for (int part = 0; part < 4; part++) {
                int nf = kc * 2 + (part >> 1);
                int e = (part & 1) * 2;
                float p0 = sacc[nf][e], p1 = sacc[nf][e + 1];
                __nv_bfloat16 h0, l0, h1, l1;
                split_bf16(p0, h0, l0);
                split_bf16(p1, h1, l1);
                __nv_bfloat162 vh2 = {h0, h1}, vl2 = {l0, l1};
                pfh[kc][part] = *(uint32_t*)&vh2;
                pfl[kc][part] = *(uint32_t*)&vl2;
            }
        }

#pragma unroll
        for (int kc = 0; kc < 4; kc++) {
            uint32_t vh[4][4], vl[4][4];
#pragma unroll
            for (int idx = 0; idx < 4; idx++) {
                int vg = idx >> 1, half = idx & 1;
                int rowV = kc * 16 + (lane & 7) + ((lane >> 3) & 1) * 8;
                int c16 = vg * 4 + half * 2 + (lane >> 4);
                uint32_t ad = (uint32_t)(rowV * 128 + ((c16 ^ (rowV & 7)) * 16));
                ldsm4t(vh[idx], stg + AOFF_VH + ad);
                ldsm4t(vl[idx], stg + AOFF_VL + ad);
            }
#pragma unroll
            for (int idx = 0; idx < 4; idx++) {
                int nf0 = (idx >> 1) * 4 + (idx & 1) * 2;
                mma_bf16(oacc[nf0], pfh[kc], vh[idx][0], vh[idx][1]);
                mma_bf16(oacc[nf0 + 1], pfh[kc], vh[idx][2], vh[idx][3]);
            }
#pragma unroll
            for (int idx = 0; idx < 4; idx++) {
                int nf0 = (idx >> 1) * 4 + (idx & 1) * 2;
                mma_bf16(oacc[nf0], pfh[kc], vl[idx][0], vl[idx][1]);
                mma_bf16(oacc[nf0 + 1], pfh[kc], vl[idx][2], vl[idx][3]);
            }
#pragma unroll
            for (int idx = 0; idx < 4; idx++) {
                int nf0 = (idx >> 1) * 4 + (idx & 1) * 2;
                mma_bf16(oacc[nf0], pfl[kc], vh[idx][0], vh[idx][1]);
                mma_bf16(oacc[nf0 + 1], pfl[kc], vh[idx][2], vh[idx][3]);
            }
        }
        __syncthreads();
    }

#pragma unroll
    for (int r = 0; r < 2; r++) {
        float inv = 1.0f / lrow[r];
        size_t row = (size_t)(b * Tz + q0 + wid * 16 + grp + r * 8);
#pragma unroll
        for (int nf = 0; nf < 8; nf++) {
            float v0 = oacc[nf][2 * r] * inv;
            float v1 = oacc[nf][2 * r + 1] * inv;
            __nv_bfloat16 h0, l0, h1, l1;
            split_bf16(v0, h0, l0);
            split_bf16(v1, h1, l1);
            __nv_bfloat162 ph = {h0, h1}, pl = {l0, l1};
            size_t o = row * Cz + h * HDz + nf * 8 + lm2;
            *(uint32_t*)&oh[o] = *(uint32_t*)&ph;
            *(uint32_t*)&ol[o] = *(uint32_t*)&pl;
        }
    }
}

// ---------------------------------------------------------------------------
// Launch
// ---------------------------------------------------------------------------
extern "C" void kernel_launch(void* const* d_in, const int* in_sizes, int n_in,
                              void* d_out, int out_size) {
    const float* x      = (const float*)d_in[0];
    const float* W_attn = (const float*)d_in[1];
    const float* b_attn = (const float*)d_in[2];
    const float* W_proj = (const float*)d_in[3];
    const float* b_proj = (const float*)d_in[4];
    float* out = (float*)d_out;

    __half *xh, *xl, *wah;
    __nv_bfloat16 *qkvh, *qkvl, *ath, *atl, *wph, *wpl;
    cudaGetSymbolAddress((void**)&xh, g_xh);
    cudaGetSymbolAddress((void**)&xl, g_xl);
    cudaGetSymbolAddress((void**)&wah, g_wah);
    cudaGetSymbolAddress((void**)&qkvh, g_qkvh);
    cudaGetSymbolAddress((void**)&qkvl, g_qkvl);
    cudaGetSymbolAddress((void**)&ath, g_ath);
    cudaGetSymbolAddress((void**)&atl, g_atl);
    cudaGetSymbolAddress((void**)&wph, g_wph);
    cudaGetSymbolAddress((void**)&wpl, g_wpl);

    cudaFuncSetAttribute(tc_gemm_f16, cudaFuncAttributeMaxDynamicSharedMemorySize, GEMM2_SMEM);
    cudaFuncSetAttribute(tc_gemm, cudaFuncAttributeMaxDynamicSharedMemorySize, GEMM_SMEM);
    cudaFuncSetAttribute(attn_tc, cudaFuncAttributeMaxDynamicSharedMemorySize, ATT_SMEM);

    const int n4 = Mz * Cz / 4;

    split_f16_kernel<<<n4 / 256, 256>>>(x, xh, xl, n4);
    tsplit_f16_kernel<<<dim3(N_QKV / 32, Cz / 32), dim3(32, 8)>>>(W_attn, wah, Cz, N_QKV);
    tsplit_kernel<<<dim3(Cz / 32, Cz / 32), dim3(32, 8)>>>(W_proj, wph, wpl, Cz, Cz);

    // 1) QKV projection: fp16 2-term -> split bf16 output
    tc_gemm_f16<<<dim3(N_QKV / 128, Mz / 128), 256, GEMM2_SMEM>>>(
        xh, xl, wah, b_attn, qkvh, qkvl, N_QKV, Cz);

    // 2) Tensor-core causal attention (bf16 3-term) -> split bf16 output
    attn_tc<<<dim3(Tz / 128, Bz * NHz), 256, ATT_SMEM>>>(qkvh, qkvl, ath, atl);

    // 3) Output projection: bf16 3-term -> fp32
    tc_gemm<<<dim3(Cz / 128, Mz / 128), 256, GEMM_SMEM>>>(
        ath, atl, wph, wpl, b_proj, out, Cz, Cz);
}

// round 13
// speedup vs baseline: 1.0084x; 1.0084x over previous
#include <cuda_runtime.h>
#include <cuda_bf16.h>
#include <cuda_fp16.h>
#include <cstdint>

// Problem constants
#define Bz 8
#define Tz 1024
#define Cz 768
#define NHz 12
#define HDz 64
#define Mz (Bz * Tz)          // 8192
#define N_QKV (3 * Cz)        // 2304

// Scratch in device globals (no allocations allowed)
__device__ __half g_xh[(size_t)Mz * Cz], g_xl[(size_t)Mz * Cz];
__device__ __half g_wah[(size_t)N_QKV * Cz];
__device__ __nv_bfloat16 g_qkvh[(size_t)Mz * N_QKV], g_qkvl[(size_t)Mz * N_QKV];
__device__ __nv_bfloat16 g_ath[(size_t)Mz * Cz], g_atl[(size_t)Mz * Cz];
__device__ __nv_bfloat16 g_wph[(size_t)Cz * Cz], g_wpl[(size_t)Cz * Cz];

// ---------------------------------------------------------------------------
// Base-ISA helpers
// ---------------------------------------------------------------------------
__device__ __forceinline__ uint32_t smem_u32(const void* p) {
    uint32_t a;
    asm("{ .reg .u64 t; cvta.to.shared.u64 t, %1; cvt.u32.u64 %0, t; }"
        : "=r"(a) : "l"(p));
    return a;
}
__device__ __forceinline__ void cpa16(uint32_t s, const void* g) {
    asm volatile("cp.async.cg.shared.global [%0], [%1], 16;" :: "r"(s), "l"(g));
}
#define CPCOMMIT() asm volatile("cp.async.commit_group;" ::: "memory")
template <int N> __device__ __forceinline__ void cpwait() {
    asm volatile("cp.async.wait_group %0;" :: "n"(N) : "memory");
}
__device__ __forceinline__ void ldsm4(uint32_t* r, uint32_t addr) {
    asm volatile("ldmatrix.sync.aligned.m8n8.x4.shared.b16 {%0,%1,%2,%3}, [%4];"
                 : "=r"(r[0]), "=r"(r[1]), "=r"(r[2]), "=r"(r[3]) : "r"(addr));
}
__device__ __forceinline__ void ldsm4t(uint32_t* r, uint32_t addr) {
    asm volatile("ldmatrix.sync.aligned.m8n8.x4.trans.shared.b16 {%0,%1,%2,%3}, [%4];"
                 : "=r"(r[0]), "=r"(r[1]), "=r"(r[2]), "=r"(r[3]) : "r"(addr));
}
__device__ __forceinline__ void mma_bf16(float* d, const uint32_t* a,
                                         uint32_t b0, uint32_t b1) {
    asm("mma.sync.aligned.m16n8k16.row.col.f32.bf16.bf16.f32 "
        "{%0,%1,%2,%3}, {%4,%5,%6,%7}, {%8,%9}, {%0,%1,%2,%3};"
        : "+f"(d[0]), "+f"(d[1]), "+f"(d[2]), "+f"(d[3])
        : "r"(a[0]), "r"(a[1]), "r"(a[2]), "r"(a[3]), "r"(b0), "r"(b1));
}
__device__ __forceinline__ void mma_f16(float* d, const uint32_t* a,
                                        uint32_t b0, uint32_t b1) {
    asm("mma.sync.aligned.m16n8k16.row.col.f32.f16.f16.f32 "
        "{%0,%1,%2,%3}, {%4,%5,%6,%7}, {%8,%9}, {%0,%1,%2,%3};"
        : "+f"(d[0]), "+f"(d[1]), "+f"(d[2]), "+f"(d[3])
        : "r"(a[0]), "r"(a[1]), "r"(a[2]), "r"(a[3]), "r"(b0), "r"(b1));
}
__device__ __forceinline__ void split_bf16(float v, __nv_bfloat16& h, __nv_bfloat16& l) {
    h = __float2bfloat16(v);
    l = __float2bfloat16(v - __bfloat162float(h));
}
__device__ __forceinline__ void split_f16(float v, __half& h, __half& l) {
    h = __float2half(v);
    l = __float2half(v - __half2float(h));
}

// ---------------------------------------------------------------------------
// Prep kernels
// ---------------------------------------------------------------------------
__global__ __launch_bounds__(256)
void split_f16_kernel(const float* __restrict__ in, __half* __restrict__ oh,
                      __half* __restrict__ ol, int n4) {
    int i = blockIdx.x * 256 + threadIdx.x;
    if (i >= n4) return;
    float4 v = *(const float4*)(in + (size_t)i * 4);
    __half h[4], l[4];
    split_f16(v.x, h[0], l[0]);
    split_f16(v.y, h[1], l[1]);
    split_f16(v.z, h[2], l[2]);
    split_f16(v.w, h[3], l[3]);
    *(uint2*)(oh + (size_t)i * 4) = *(uint2*)h;
    *(uint2*)(ol + (size_t)i * 4) = *(uint2*)l;
}

// W [K,N] fp32 -> transposed fp16 [N,K] (hi only)
__global__ void tsplit_f16_kernel(const float* __restrict__ W,
                                  __half* __restrict__ oh, int K, int N) {
    __shared__ float t[32][33];
    int n0 = blockIdx.x * 32, k0 = blockIdx.y * 32;
    int tx = threadIdx.x, ty = threadIdx.y;
#pragma unroll
    for (int r = 0; r < 32; r += 8)
        t[ty + r][tx] = W[(size_t)(k0 + ty + r) * N + n0 + tx];
    __syncthreads();
#pragma unroll
    for (int r = 0; r < 32; r += 8) {
        oh[(size_t)(n0 + ty + r) * K + k0 + tx] = __float2half(t[tx][ty + r]);
    }
}

// W [K,N] fp32 -> transposed split bf16 [N,K]
__global__ void tsplit_kernel(const float* __restrict__ W,
                              __nv_bfloat16* __restrict__ oh,
                              __nv_bfloat16* __restrict__ ol, int K, int N) {
    __shared__ float t[32][33];
    int n0 = blockIdx.x * 32, k0 = blockIdx.y * 32;
    int tx = threadIdx.x, ty = threadIdx.y;
#pragma unroll
    for (int r = 0; r < 32; r += 8)
        t[ty + r][tx] = W[(size_t)(k0 + ty + r) * N + n0 + tx];
    __syncthreads();
#pragma unroll
    for (int r = 0; r < 32; r += 8) {
        float v = t[tx][ty + r];
        __nv_bfloat16 h, l;
        split_bf16(v, h, l);
        size_t o = (size_t)(n0 + ty + r) * K + k0 + tx;
        oh[o] = h;
        ol[o] = l;
    }
}

__device__ __forceinline__ uint32_t sw64(int row, int c16) {
    return (uint32_t)(row * 64 + ((c16 ^ ((row >> 1) & 3)) * 16));
}

// ---------------------------------------------------------------------------
// fp16 2-term GEMM (QKV): C = (Ah+Al) @ Bh^T + bias -> split bf16 out.
// 128x128 CTA tile, 8 warps (64x32 each), BK=32, 3-stage cp.async ring.
// Stage = Ah(8K) + Al(8K) + Bh(8K) = 24KB.
// ---------------------------------------------------------------------------
#define STAGE2_B 24576
#define NSTAGE 3
#define OFF2_AH 0
#define OFF2_AL 8192
#define OFF2_BH 16384
#define GEMM2_SMEM (NSTAGE * STAGE2_B)   // 73728

__global__ __launch_bounds__(256)
void tc_gemm_f16(const __half* __restrict__ Ah, const __half* __restrict__ Al,
                 const __half* __restrict__ Bh, const float* __restrict__ bias,
                 __nv_bfloat16* __restrict__ Ch, __nv_bfloat16* __restrict__ Cl,
                 int N, int K) {
    extern __shared__ char smp[];
    const uint32_t sb = smem_u32(smp);

    const int tid = threadIdx.x;
    const int wid = tid >> 5;
    const int lane = tid & 31;
    const int wm = wid & 1;
    const int wn = wid >> 1;
    const int bm = blockIdx.y * 128;
    const int bn = blockIdx.x * 128;
    const int NKC = K >> 5;

    const int lrow0 = tid >> 2;    // 0..63
    const int lc16 = tid & 3;      // 0..3

    const int rowA = wm * 64 + (lane & 15);
    const int rowB = wn * 32 + (lane & 15);
    const int rswA = (rowA >> 1) & 3;
    const int rswB = (rowB >> 1) & 3;
    const int chalf = lane >> 4;

    float acc[4][4][4];
#pragma unroll
    for (int i = 0; i < 4; i++)
#pragma unroll
        for (int j = 0; j < 4; j++)
#pragma unroll
            for (int e = 0; e < 4; e++) acc[i][j][e] = 0.0f;

    auto load_stage = [&](int kc) {
        const uint32_t stg = sb + (uint32_t)(kc % NSTAGE) * STAGE2_B;
        const int ke = kc * 32;
#pragma unroll
        for (int v = 0; v < 2; v++) {
            int row = lrow0 + v * 64;
            uint32_t swo = sw64(row, lc16);
            size_t ga = (size_t)(bm + row) * K + ke + lc16 * 8;
            size_t gb = (size_t)(bn + row) * K + ke + lc16 * 8;
            cpa16(stg + OFF2_AH + swo, Ah + ga);
            cpa16(stg + OFF2_AL + swo, Al + ga);
            cpa16(stg + OFF2_BH + swo, Bh + gb);
        }
    };

    load_stage(0);
    CPCOMMIT();
    load_stage(1);
    CPCOMMIT();

    for (int kc = 0; kc < NKC; kc++) {
        if (kc + 1 < NKC) cpwait<1>();
        else              cpwait<0>();
        __syncthreads();              // publish stage kc; readers of kc-1 done
        if (kc + 2 < NKC) {
            load_stage(kc + 2);
            CPCOMMIT();
        }

        const uint32_t stg = sb + (uint32_t)(kc % NSTAGE) * STAGE2_B;
#pragma unroll
        for (int s16 = 0; s16 < 2; s16++) {
            const int c16 = s16 * 2 + chalf;
            const uint32_t aswc = (uint32_t)((c16 ^ rswA) * 16);
            const uint32_t bswc = (uint32_t)((c16 ^ rswB) * 16);

            uint32_t ah[4][4], al[4][4], bh[2][4];
#pragma unroll
            for (int i = 0; i < 4; i++) {
                uint32_t ro = (uint32_t)((rowA + 16 * i) * 64);
                ldsm4(ah[i], stg + OFF2_AH + ro + aswc);
                ldsm4(al[i], stg + OFF2_AL + ro + aswc);
            }
#pragma unroll
            for (int g = 0; g < 2; g++) {
                uint32_t ro = (uint32_t)((rowB + 16 * g) * 64);
                ldsm4(bh[g], stg + OFF2_BH + ro + bswc);
            }

#pragma unroll
            for (int i = 0; i < 4; i++)
#pragma unroll
                for (int g = 0; g < 2; g++)
#pragma unroll
                    for (int h = 0; h < 2; h++)
                        mma_f16(acc[i][g * 2 + h], ah[i], bh[g][h], bh[g][h + 2]);
#pragma unroll
            for (int i = 0; i < 4; i++)
#pragma unroll
                for (int g = 0; g < 2; g++)
#pragma unroll
                    for (int h = 0; h < 2; h++)
                        mma_f16(acc[i][g * 2 + h], al[i], bh[g][h], bh[g][h + 2]);
        }
    }

    const int lane4 = lane >> 2;
    const int lm2 = (lane & 3) * 2;
#pragma unroll
    for (int i = 0; i < 4; i++) {
        int r0 = bm + wm * 64 + i * 16 + lane4;
#pragma unroll
        for (int j = 0; j < 4; j++) {
            int cc = bn + wn * 32 + j * 8 + lm2;
            float b0 = bias[cc], b1 = bias[cc + 1];
            float v00 = acc[i][j][0] + b0, v01 = acc[i][j][1] + b1;
            float v10 = acc[i][j][2] + b0, v11 = acc[i][j][3] + b1;
            __nv_bfloat16 h0, l0, h1, l1;
            split_bf16(v00, h0, l0);
            split_bf16(v01, h1, l1);
            __nv_bfloat162 ph = {h0, h1}, pl = {l0, l1};
            *(uint32_t*)&Ch[(size_t)r0 * N + cc] = *(uint32_t*)&ph;
            *(uint32_t*)&Cl[(size_t)r0 * N + cc] = *(uint32_t*)&pl;
            split_bf16(v10, h0, l0);
            split_bf16(v11, h1, l1);
            __nv_bfloat162 qh = {h0, h1}, ql = {l0, l1};
            *(uint32_t*)&Ch[(size_t)(r0 + 8) * N + cc] = *(uint32_t*)&qh;
            *(uint32_t*)&Cl[(size_t)(r0 + 8) * N + cc] = *(uint32_t*)&ql;
        }
    }
}

// ---------------------------------------------------------------------------
// bf16 3-term GEMM (proj): R9-verified, fp32 out.
// ---------------------------------------------------------------------------
#define STAGE_B 32768
#define OFF_AH 0
#define OFF_AL 8192
#define OFF_BH 16384
#define OFF_BL 24576
#define GEMM_SMEM (NSTAGE * STAGE_B)     // 98304

__global__ __launch_bounds__(256)
void tc_gemm(const __nv_bfloat16* __restrict__ Ah, const __nv_bfloat16* __restrict__ Al,
             const __nv_bfloat16* __restrict__ Bh, const __nv_bfloat16* __restrict__ Bl,
             const float* __restrict__ bias, float* __restrict__ C, int N, int K) {
    extern __shared__ char smp[];
    const uint32_t sb = smem_u32(smp);

    const int tid = threadIdx.x;
    const int wid = tid >> 5;
    const int lane = tid & 31;
    const int wm = wid & 1;
    const int wn = wid >> 1;
    const int bm = blockIdx.y * 128;
    const int bn = blockIdx.x * 128;
    const int NKC = K >> 5;

    const int lrow0 = tid >> 2;
    const int lc16 = tid & 3;

    const int rowA = wm * 64 + (lane & 15);
    const int rowB = wn * 32 + (lane & 15);
    const int rswA = (rowA >> 1) & 3;
    const int rswB = (rowB >> 1) & 3;
    const int chalf = lane >> 4;

    float acc[4][4][4];
#pragma unroll
    for (int i = 0; i < 4; i++)
#pragma unroll
        for (int j = 0; j < 4; j++)
#pragma unroll
            for (int e = 0; e < 4; e++) acc[i][j][e] = 0.0f;

    auto load_stage = [&](int kc) {
        const uint32_t stg = sb + (uint32_t)(kc % NSTAGE) * STAGE_B;
        const int ke = kc * 32;
#pragma unroll
        for (int v = 0; v < 2; v++) {
            int row = lrow0 + v * 64;
            uint32_t swo = sw64(row, lc16);
            size_t ga = (size_t)(bm + row) * K + ke + lc16 * 8;
            size_t gb = (size_t)(bn + row) * K + ke + lc16 * 8;
            cpa16(stg + OFF_AH + swo, Ah + ga);
            cpa16(stg + OFF_AL + swo, Al + ga);
            cpa16(stg + OFF_BH + swo, Bh + gb);
            cpa16(stg + OFF_BL + swo, Bl + gb);
        }
    };

    load_stage(0);
    CPCOMMIT();
    load_stage(1);
    CPCOMMIT();

    for (int kc = 0; kc < NKC; kc++) {
        if (kc + 1 < NKC) cpwait<1>();
        else              cpwait<0>();
        __syncthreads();
        if (kc + 2 < NKC) {
            load_stage(kc + 2);
            CPCOMMIT();
        }

        const uint32_t stg = sb + (uint32_t)(kc % NSTAGE) * STAGE_B;
#pragma unroll
        for (int s16 = 0; s16 < 2; s16++) {
            const int c16 = s16 * 2 + chalf;
            const uint32_t aswc = (uint32_t)((c16 ^ rswA) * 16);
            const uint32_t bswc = (uint32_t)((c16 ^ rswB) * 16);

            uint32_t ah[4][4], al[4][4], bh[2][4], bl[2][4];
#pragma unroll
            for (int i = 0; i < 4; i++) {
                uint32_t ro = (uint32_t)((rowA + 16 * i) * 64);
                ldsm4(ah[i], stg + OFF_AH + ro + aswc);
                ldsm4(al[i], stg + OFF_AL + ro + aswc);
            }
#pragma unroll
            for (int g = 0; g < 2; g++) {
                uint32_t ro = (uint32_t)((rowB + 16 * g) * 64);
                ldsm4(bh[g], stg + OFF_BH + ro + bswc);
                ldsm4(bl[g], stg + OFF_BL + ro + bswc);
            }

#pragma unroll
            for (int i = 0; i < 4; i++)
#pragma unroll
                for (int g = 0; g < 2; g++)
#pragma unroll
                    for (int h = 0; h < 2; h++)
                        mma_bf16(acc[i][g * 2 + h], ah[i], bh[g][h], bh[g][h + 2]);
#pragma unroll
            for (int i = 0; i < 4; i++)
#pragma unroll
                for (int g = 0; g < 2; g++)
#pragma unroll
                    for (int h = 0; h < 2; h++)
                        mma_bf16(acc[i][g * 2 + h], ah[i], bl[g][h], bl[g][h + 2]);
#pragma unroll
            for (int i = 0; i < 4; i++)
#pragma unroll
                for (int g = 0; g < 2; g++)
#pragma unroll
                    for (int h = 0; h < 2; h++)
                        mma_bf16(acc[i][g * 2 + h], al[i], bh[g][h], bh[g][h + 2]);
        }
    }

    const int lane4 = lane >> 2;
    const int lm2 = (lane & 3) * 2;
#pragma unroll
    for (int i = 0; i < 4; i++) {
        int r0 = bm + wm * 64 + i * 16 + lane4;
#pragma unroll
        for (int j = 0; j < 4; j++) {
            int cc = bn + wn * 32 + j * 8 + lm2;
            float b0 = bias[cc], b1 = bias[cc + 1];
            *(float2*)&C[(size_t)r0 * N + cc] = {acc[i][j][0] + b0, acc[i][j][1] + b1};
            *(float2*)&C[(size_t)(r0 + 8) * N + cc] = {acc[i][j][2] + b0, acc[i][j][3] + b1};
        }
    }
}

// ---------------------------------------------------------------------------
// Tensor-core causal flash attention (R7/R9-verified; big q-tiles first)
// ---------------------------------------------------------------------------
#define AOFF_QH 0
#define AOFF_QL 16384
#define AOFF_KV 32768
#define ASTG 32768
#define AOFF_KH 0
#define AOFF_KL 8192
#define AOFF_VH 16384
#define AOFF_VL 24576
#define ATT_SMEM (AOFF_KV + 2 * ASTG)   // 98304

__device__ __forceinline__ uint32_t asw(int row, int c16) {
    return (uint32_t)(row * 128 + ((c16 ^ (row & 7)) * 16));
}

__global__ __launch_bounds__(256)
void attn_tc(const __nv_bfloat16* __restrict__ qh,
             const __nv_bfloat16* __restrict__ ql,
             __nv_bfloat16* __restrict__ oh, __nv_bfloat16* __restrict__ ol) {
    extern __shared__ char smp[];
    const uint32_t sb = smem_u32(smp);

    const int tid = threadIdx.x;
    const int wid = tid >> 5;
    const int lane = tid & 31;
    const int bh = blockIdx.y;
    const int b = bh / NHz;
    const int h = bh % NHz;
    const int q0 = ((int)gridDim.x - 1 - (int)blockIdx.x) * 128;  // big tiles first

    const __nv_bfloat16* qbh = qh + (size_t)b * Tz * N_QKV + h * HDz;
    const __nv_bfloat16* qbl = ql + (size_t)b * Tz * N_QKV + h * HDz;

#pragma unroll
    for (int i = 0; i < 4; i++) {
        int idx = tid + i * 256;
        int row = idx >> 3;
        int c = idx & 7;
        uint32_t swo = asw(row, c);
        size_t g = (size_t)(q0 + row) * N_QKV + c * 8;
        cpa16(sb + AOFF_QH + swo, qbh + g);
        cpa16(sb + AOFF_QL + swo, qbl + g);
    }
    CPCOMMIT();

    auto load_kv = [&](int kt) {
        const uint32_t stg = sb + AOFF_KV + (uint32_t)(kt & 1) * ASTG;
        const int k0 = kt * 64;
#pragma unroll
        for (int v = 0; v < 2; v++) {
            int row = (tid >> 3) + v * 32;
            int c = tid & 7;
            uint32_t swo = asw(row, c);
            size_t g = (size_t)(k0 + row) * N_QKV + c * 8;
            cpa16(stg + AOFF_KH + swo, qbh + g + Cz);
            cpa16(stg + AOFF_KL + swo, qbl + g + Cz);
            cpa16(stg + AOFF_VH + swo, qbh + g + 2 * Cz);
            cpa16(stg + AOFF_VL + swo, qbl + g + 2 * Cz);
        }
    };

    load_kv(0);
    CPCOMMIT();
    cpwait<1>();        // Q arrived
    __syncthreads();

    const int rowQ = wid * 16 + (lane & 15);
    const int chalf = lane >> 4;
    const int grp = lane >> 2;
    const int lm2 = (lane & 3) * 2;

    float oacc[8][4];
#pragma unroll
    for (int nf = 0; nf < 8; nf++)
#pragma unroll
        for (int e = 0; e < 4; e++) oacc[nf][e] = 0.0f;
    float mrow[2] = {-1e30f, -1e30f};
    float lrow[2] = {0.0f, 0.0f};

    const int ntiles = (q0 + 128) / 64;
    for (int kt = 0; kt < ntiles; kt++) {
        if (kt + 1 < ntiles) {
            load_kv(kt + 1);
            CPCOMMIT();
            cpwait<1>();
        } else {
            cpwait<0>();
        }
        __syncthreads();

        const uint32_t stg = sb + AOFF_KV + (uint32_t)(kt & 1) * ASTG;
        const int k0 = kt * 64;

        float sacc[8][4];
#pragma unroll
        for (int nf = 0; nf < 8; nf++)
#pragma unroll
            for (int e = 0; e < 4; e++) sacc[nf][e] = 0.0f;

#pragma unroll
        for (int kc = 0; kc < 4; kc++) {
            int c16 = kc * 2 + chalf;
            uint32_t qad = (uint32_t)(rowQ * 128 + ((c16 ^ (rowQ & 7)) * 16));
            uint32_t qfh[4], qfl[4];
            ldsm4(qfh, sb + AOFF_QH + qad);
            ldsm4(qfl, sb + AOFF_QL + qad);

            uint32_t kh[4][4], kl[4][4];
#pragma unroll
            for (int g = 0; g < 4; g++) {
                int rowK = g * 16 + (lane & 15);
                uint32_t ad = (uint32_t)(rowK * 128 + ((c16 ^ (rowK & 7)) * 16));
                ldsm4(kh[g], stg + AOFF_KH + ad);
                ldsm4(kl[g], stg + AOFF_KL + ad);
            }
#pragma unroll
            for (int g = 0; g < 4; g++)
#pragma unroll
                for (int hh = 0; hh < 2; hh++)
                    mma_bf16(sacc[g * 2 + hh], qfh, kh[g][hh], kh[g][hh + 2]);
#pragma unroll
            for (int g = 0; g < 4; g++)
#pragma unroll
                for (int hh = 0; hh < 2; hh++)
                    mma_bf16(sacc[g * 2 + hh], qfh, kl[g][hh], kl[g][hh + 2]);
#pragma unroll
            for (int g = 0; g < 4; g++)
#pragma unroll
                for (int hh = 0; hh < 2; hh++)
                    mma_bf16(sacc[g * 2 + hh], qfl, kh[g][hh], kh[g][hh + 2]);
        }

        const bool domask = (k0 + 63 > q0);
#pragma unroll
        for (int nf = 0; nf < 8; nf++)
#pragma unroll
            for (int e = 0; e < 4; e++) {
                float s = sacc[nf][e] * 0.125f;
                if (domask) {
                    int kcol = k0 + nf * 8 + lm2 + (e & 1);
                    int qrow = q0 + wid * 16 + grp + ((e >> 1) << 3);
                    if (kcol > qrow) s = -1e30f;
                }
                sacc[nf][e] = s;
            }

#pragma unroll
        for (int r = 0; r < 2; r++) {
            float mt = -1e30f;
#pragma unroll
            for (int nf = 0; nf < 8; nf++)
                mt = fmaxf(mt, fmaxf(sacc[nf][2 * r], sacc[nf][2 * r + 1]));
            mt = fmaxf(mt, __shfl_xor_sync(0xffffffffu, mt, 1));
            mt = fmaxf(mt, __shfl_xor_sync(0xffffffffu, mt, 2));
            float mnew = fmaxf(mrow[r], mt);
            float alpha = __expf(mrow[r] - mnew);
            float ls = 0.0f;
#pragma unroll
            for (int nf = 0; nf < 8; nf++) {
                float p0 = __expf(sacc[nf][2 * r] - mnew);
                float p1 = __expf(sacc[nf][2 * r + 1] - mnew);
                sacc[nf][2 * r] = p0;
                sacc[nf][2 * r + 1] = p1;
                ls += p0 + p1;
            }
            ls += __shfl_xor_sync(0xffffffffu, ls, 1);
            ls += __shfl_xor_sync(0xffffffffu, ls, 2);
            lrow[r] = lrow[r] * alpha + ls;
            mrow[r] = mnew;
#pragma unroll
            for (int nf = 0; nf < 8; nf++) {
                oacc[nf][2 * r] *= alpha;
                oacc[nf][2 * r + 1] *= alpha;
            }
        }

        uint32_t pfh[4][4], pfl[4][4];
#pragma unroll
        for (int kc = 0; kc < 4; kc++) {
#pragma unroll
            for (int part = 0; part < 4; part++) {
                int nf = kc * 2 + (part >> 1);
                int e = (part & 1) * 2;
                float p0 = sacc[nf][e], p1 = sacc[nf][e + 1];
                __nv_bfloat16 h0, l0, h1, l1;
                split_bf16(p0, h0, l0);
                split_bf16(p1, h1, l1);
                __nv_bfloat162 vh2 = {h0, h1}, vl2 = {l0, l1};
                pfh[kc][part] = *(uint32_t*)&vh2;
                pfl[kc][part] = *(uint32_t*)&vl2;
            }
        }

#pragma unroll
        for (int kc = 0; kc < 4; kc++) {
            uint32_t vh[4][4], vl[4][4];
#pragma unroll
            for (int idx = 0; idx < 4; idx++) {
                int vg = idx >> 1, half = idx & 1;
                int rowV = kc * 16 + (lane & 7) + ((lane >> 3) & 1) * 8;
                int c16 = vg * 4 + half * 2 + (lane >> 4);
                uint32_t ad = (uint32_t)(rowV * 128 + ((c16 ^ (rowV & 7)) * 16));
                ldsm4t(vh[idx], stg + AOFF_VH + ad);
                ldsm4t(vl[idx], stg + AOFF_VL + ad);
            }
#pragma unroll
            for (int idx = 0; idx < 4; idx++) {
                int nf0 = (idx >> 1) * 4 + (idx & 1) * 2;
                mma_bf16(oacc[nf0], pfh[kc], vh[idx][0], vh[idx][1]);
                mma_bf16(oacc[nf0 + 1], pfh[kc], vh[idx][2], vh[idx][3]);
            }
#pragma unroll
            for (int idx = 0; idx < 4; idx++) {
                int nf0 = (idx >> 1) * 4 + (idx & 1) * 2;
                mma_bf16(oacc[nf0], pfh[kc], vl[idx][0], vl[idx][1]);
                mma_bf16(oacc[nf0 + 1], pfh[kc], vl[idx][2], vl[idx][3]);
            }
#pragma unroll
            for (int idx = 0; idx < 4; idx++) {
                int nf0 = (idx >> 1) * 4 + (idx & 1) * 2;
                mma_bf16(oacc[nf0], pfl[kc], vh[idx][0], vh[idx][1]);
                mma_bf16(oacc[nf0 + 1], pfl[kc], vh[idx][2], vh[idx][3]);
            }
        }
        __syncthreads();
    }

#pragma unroll
    for (int r = 0; r < 2; r++) {
        float inv = 1.0f / lrow[r];
        size_t row = (size_t)(b * Tz + q0 + wid * 16 + grp + r * 8);
#pragma unroll
        for (int nf = 0; nf < 8; nf++) {
            float v0 = oacc[nf][2 * r] * inv;
            float v1 = oacc[nf][2 * r + 1] * inv;
            __nv_bfloat16 h0, l0, h1, l1;
            split_bf16(v0, h0, l0);
            split_bf16(v1, h1, l1);
            __nv_bfloat162 ph = {h0, h1}, pl = {l0, l1};
            size_t o = row * Cz + h * HDz + nf * 8 + lm2;
            *(uint32_t*)&oh[o] = *(uint32_t*)&ph;
            *(uint32_t*)&ol[o] = *(uint32_t*)&pl;
        }
    }
}

// ---------------------------------------------------------------------------
// Launch
// ---------------------------------------------------------------------------
extern "C" void kernel_launch(void* const* d_in, const int* in_sizes, int n_in,
                              void* d_out, int out_size) {
    const float* x      = (const float*)d_in[0];
    const float* W_attn = (const float*)d_in[1];
    const float* b_attn = (const float*)d_in[2];
    const float* W_proj = (const float*)d_in[3];
    const float* b_proj = (const float*)d_in[4];
    float* out = (float*)d_out;

    __half *xh, *xl, *wah;
    __nv_bfloat16 *qkvh, *qkvl, *ath, *atl, *wph, *wpl;
    cudaGetSymbolAddress((void**)&xh, g_xh);
    cudaGetSymbolAddress((void**)&xl, g_xl);
    cudaGetSymbolAddress((void**)&wah, g_wah);
    cudaGetSymbolAddress((void**)&qkvh, g_qkvh);
    cudaGetSymbolAddress((void**)&qkvl, g_qkvl);
    cudaGetSymbolAddress((void**)&ath, g_ath);
    cudaGetSymbolAddress((void**)&atl, g_atl);
    cudaGetSymbolAddress((void**)&wph, g_wph);
    cudaGetSymbolAddress((void**)&wpl, g_wpl);

    cudaFuncSetAttribute(tc_gemm_f16, cudaFuncAttributeMaxDynamicSharedMemorySize, GEMM2_SMEM);
    cudaFuncSetAttribute(tc_gemm, cudaFuncAttributeMaxDynamicSharedMemorySize, GEMM_SMEM);
    cudaFuncSetAttribute(attn_tc, cudaFuncAttributeMaxDynamicSharedMemorySize, ATT_SMEM);

    const int n4 = Mz * Cz / 4;

    split_f16_kernel<<<n4 / 256, 256>>>(x, xh, xl, n4);
    tsplit_f16_kernel<<<dim3(N_QKV / 32, Cz / 32), dim3(32, 8)>>>(W_attn, wah, Cz, N_QKV);
    tsplit_kernel<<<dim3(Cz / 32, Cz / 32), dim3(32, 8)>>>(W_proj, wph, wpl, Cz, Cz);

    // 1) QKV projection: fp16 2-term -> split bf16 output
    tc_gemm_f16<<<dim3(N_QKV / 128, Mz / 128), 256, GEMM2_SMEM>>>(
        xh, xl, wah, b_attn, qkvh, qkvl, N_QKV, Cz);

    // 2) Tensor-core causal attention (bf16 3-term) -> split bf16 output
    attn_tc<<<dim3(Tz / 128, Bz * NHz), 256, ATT_SMEM>>>(qkvh, qkvl, ath, atl);

    // 3) Output projection: bf16 3-term -> fp32
    tc_gemm<<<dim3(Cz / 128, Mz / 128), 256, GEMM_SMEM>>>(
        ath, atl, wph, wpl, b_proj, out, Cz, Cz);
}